// round 2
// baseline (speedup 1.0000x reference)
#include <cuda_runtime.h>
#include <cuda_fp16.h>

#define N_NODES 100000
#define N_EDGES 1600000
#define D 48
#define D4 (D / 4)    // 12 float4 chunks per fp32 row
#define D8 (D / 8)    // 6 chunks of 8 halves per fp16 row

// Scratch: xw = x @ w stored in fp16 (9.6 MB) — __device__ global, no allocation.
__device__ __half g_xw[N_NODES * D];

// ---------------------------------------------------------------------------
// Fused: zero the output row + compute g_xw[n] = x[n] @ w (fp32 math, fp16 store)
// One thread per node. w cached in shared memory (9.2 KB).
// ---------------------------------------------------------------------------
__global__ void gemm_zero_kernel(const float* __restrict__ x,
                                 const float* __restrict__ w,
                                 float4* __restrict__ out) {
    __shared__ float ws[D * D];
    for (int i = threadIdx.x; i < D * D; i += blockDim.x) ws[i] = w[i];
    __syncthreads();

    int node = blockIdx.x * blockDim.x + threadIdx.x;
    if (node >= N_NODES) return;

    // zero this node's output row (atomics will accumulate into it)
    float4 z = make_float4(0.f, 0.f, 0.f, 0.f);
    float4* orow = out + (size_t)node * D4;
#pragma unroll
    for (int j = 0; j < D4; j++) orow[j] = z;

    // load x row
    float xr[D];
    const float4* xp = (const float4*)(x + (size_t)node * D);
#pragma unroll
    for (int k4 = 0; k4 < D4; k4++) {
        float4 v = xp[k4];
        xr[k4 * 4 + 0] = v.x;
        xr[k4 * 4 + 1] = v.y;
        xr[k4 * 4 + 2] = v.z;
        xr[k4 * 4 + 3] = v.w;
    }

    // compute + store fp16 row (48 halves = 96 B = 6 float4)
    float4* hp = (float4*)(g_xw + (size_t)node * D);
#pragma unroll
    for (int j8 = 0; j8 < D8; j8++) {
        float acc[8];
#pragma unroll
        for (int t = 0; t < 8; t++) acc[t] = 0.f;
#pragma unroll
        for (int k = 0; k < D; k++) {
            float xv = xr[k];
            const float* wrow = ws + k * D + j8 * 8;
#pragma unroll
            for (int t = 0; t < 8; t++) acc[t] = fmaf(xv, wrow[t], acc[t]);
        }
        __half2 h[4];
#pragma unroll
        for (int t = 0; t < 4; t++)
            h[t] = __floats2half2_rn(acc[2 * t], acc[2 * t + 1]);
        hp[j8] = *(const float4*)h;
    }
}

// ---------------------------------------------------------------------------
// COO scatter: out[dst] += adj_vals[e] * xw[src]  (fp16 gather, fp32 RED).
// 6 threads per edge; each thread handles 8 output columns (one float4 of halves).
// ---------------------------------------------------------------------------
__global__ void scatter_kernel(const int* __restrict__ src,
                               const int* __restrict__ dst,
                               const float* __restrict__ vals,
                               float* __restrict__ out) {
    int tid = blockIdx.x * blockDim.x + threadIdx.x;
    if (tid >= N_EDGES * D8) return;
    int e = tid / D8;
    int c = tid - e * D8;

    int s = __ldg(src + e);
    int d = __ldg(dst + e);
    float a = __ldg(vals + e);

    float4 raw = *(const float4*)(g_xw + (size_t)s * D + c * 8);
    const __half2* h = (const __half2*)&raw;
    float2 p0 = __half22float2(h[0]);
    float2 p1 = __half22float2(h[1]);
    float2 p2 = __half22float2(h[2]);
    float2 p3 = __half22float2(h[3]);

    float* p = out + (size_t)d * D + c * 8;
    asm volatile("red.global.add.v4.f32 [%0], {%1, %2, %3, %4};"
                 :: "l"(p), "f"(a * p0.x), "f"(a * p0.y),
                    "f"(a * p1.x), "f"(a * p1.y)
                 : "memory");
    asm volatile("red.global.add.v4.f32 [%0], {%1, %2, %3, %4};"
                 :: "l"(p + 4), "f"(a * p2.x), "f"(a * p2.y),
                    "f"(a * p3.x), "f"(a * p3.y)
                 : "memory");
}

// ---------------------------------------------------------------------------
// Finalize: out = relu(out + b), in place, float4-vectorized.
// ---------------------------------------------------------------------------
__global__ void finalize_kernel(float4* __restrict__ out,
                                const float4* __restrict__ b4) {
    int i = blockIdx.x * blockDim.x + threadIdx.x;
    int total = N_NODES * D4;
    if (i >= total) return;
    int c = i % D4;
    float4 bv = b4[c];
    float4 v = out[i];
    v.x = fmaxf(v.x + bv.x, 0.f);
    v.y = fmaxf(v.y + bv.y, 0.f);
    v.z = fmaxf(v.z + bv.z, 0.f);
    v.w = fmaxf(v.w + bv.w, 0.f);
    out[i] = v;
}

extern "C" void kernel_launch(void* const* d_in, const int* in_sizes, int n_in,
                              void* d_out, int out_size) {
    const float* x        = (const float*)d_in[0];
    const float* w        = (const float*)d_in[1];
    const float* b        = (const float*)d_in[2];
    const int*   edge_src = (const int*)d_in[3];
    const int*   edge_dst = (const int*)d_in[4];
    const float* adj_vals = (const float*)d_in[5];
    float* out = (float*)d_out;

    const int threads = 256;

    // 1) fused zero + xw = x @ w (fp16 store)
    {
        int blocks = (N_NODES + threads - 1) / threads;
        gemm_zero_kernel<<<blocks, threads>>>(x, w, (float4*)out);
    }
    // 2) scatter-add over edges (fp16 gather, fp32 vector RED)
    {
        int total = N_EDGES * D8;
        scatter_kernel<<<(total + threads - 1) / threads, threads>>>(
            edge_src, edge_dst, adj_vals, out);
    }
    // 3) out = relu(out + b)
    {
        int total = N_NODES * D4;
        finalize_kernel<<<(total + threads - 1) / threads, threads>>>(
            (float4*)out, (const float4*)b);
    }
}

// round 3
// speedup vs baseline: 1.2832x; 1.2832x over previous
#include <cuda_runtime.h>
#include <cuda_fp16.h>

#define N_NODES 100000
#define N_EDGES 1600000
#define D 48
#define D4 (D / 4)    // 12 float4 chunks per fp32 row

// Scratch: xw = x @ w stored in fp16 (9.6 MB) — __device__ global, no allocation.
__device__ __half g_xw[N_NODES * D];

// ---------------------------------------------------------------------------
// Zero the output buffer (coalesced; atomics accumulate into it).
// ---------------------------------------------------------------------------
__global__ void zero_kernel(float4* __restrict__ out) {
    int i = blockIdx.x * blockDim.x + threadIdx.x;
    int total = N_NODES * D4;
    if (i < total) out[i] = make_float4(0.f, 0.f, 0.f, 0.f);
}

// ---------------------------------------------------------------------------
// GEMM: g_xw[n] = x[n] @ w, fp32 math, fp16 store.
// TWO nodes per thread -> each w LDS.128 serves 8 FFMAs instead of 4.
// ---------------------------------------------------------------------------
__global__ void __launch_bounds__(256, 2)
gemm_kernel(const float* __restrict__ x, const float* __restrict__ w) {
    __shared__ float ws[D * D];
    for (int i = threadIdx.x; i < D * D; i += blockDim.x) ws[i] = w[i];
    __syncthreads();

    int base = blockIdx.x * (2 * blockDim.x) + threadIdx.x;
    int n0 = base;                  // first node
    int n1 = base + blockDim.x;     // second node
    bool has0 = (n0 < N_NODES);
    bool has1 = (n1 < N_NODES);
    if (!has0) return;

    float4 xa[D4], xb[D4];
    const float4* xp0 = (const float4*)(x + (size_t)n0 * D);
    const float4* xp1 = (const float4*)(x + (size_t)n1 * D);
#pragma unroll
    for (int k4 = 0; k4 < D4; k4++) {
        xa[k4] = xp0[k4];
        xb[k4] = has1 ? xp1[k4] : make_float4(0.f, 0.f, 0.f, 0.f);
    }

    __half* hp0 = g_xw + (size_t)n0 * D;
    __half* hp1 = g_xw + (size_t)n1 * D;

#pragma unroll
    for (int j4 = 0; j4 < D4; j4++) {
        float a0 = 0.f, a1 = 0.f, a2 = 0.f, a3 = 0.f;   // node 0
        float b0 = 0.f, b1 = 0.f, b2 = 0.f, b3 = 0.f;   // node 1
#pragma unroll
        for (int k4 = 0; k4 < D4; k4++) {
            float4 va = xa[k4];
            float4 vb = xb[k4];
#pragma unroll
            for (int t = 0; t < 4; t++) {
                int k = k4 * 4 + t;
                float xav = (t == 0) ? va.x : (t == 1) ? va.y : (t == 2) ? va.z : va.w;
                float xbv = (t == 0) ? vb.x : (t == 1) ? vb.y : (t == 2) ? vb.z : vb.w;
                float4 wr = *(const float4*)(ws + k * D + j4 * 4);
                a0 = fmaf(xav, wr.x, a0);
                a1 = fmaf(xav, wr.y, a1);
                a2 = fmaf(xav, wr.z, a2);
                a3 = fmaf(xav, wr.w, a3);
                b0 = fmaf(xbv, wr.x, b0);
                b1 = fmaf(xbv, wr.y, b1);
                b2 = fmaf(xbv, wr.z, b2);
                b3 = fmaf(xbv, wr.w, b3);
            }
        }
        __half2 ha[2], hb[2];
        ha[0] = __floats2half2_rn(a0, a1);
        ha[1] = __floats2half2_rn(a2, a3);
        hb[0] = __floats2half2_rn(b0, b1);
        hb[1] = __floats2half2_rn(b2, b3);
        *(uint2*)(hp0 + j4 * 4) = *(const uint2*)ha;
        if (has1) *(uint2*)(hp1 + j4 * 4) = *(const uint2*)hb;
    }
}

// ---------------------------------------------------------------------------
// COO scatter: out[dst] += adj_vals[e] * xw[src].
// 12 threads per edge: thread c gathers 4 halves (8 B) and issues ONE
// red.v4.f32 covering 16 B — adjacent lanes cover a contiguous 192 B row,
// letting L1tex merge adjacent 16 B lanes into 32 B L2 sector ops.
// ---------------------------------------------------------------------------
__global__ void scatter_kernel(const int* __restrict__ src,
                               const int* __restrict__ dst,
                               const float* __restrict__ vals,
                               float* __restrict__ out) {
    int tid = blockIdx.x * blockDim.x + threadIdx.x;
    if (tid >= N_EDGES * D4) return;
    int e = tid / D4;
    int c = tid - e * D4;

    int s = __ldg(src + e);
    int d = __ldg(dst + e);
    float a = __ldg(vals + e);

    uint2 raw = *(const uint2*)(g_xw + (size_t)s * D + c * 4);
    __half2 h0 = *(const __half2*)&raw.x;
    __half2 h1 = *(const __half2*)&raw.y;
    float2 f0 = __half22float2(h0);
    float2 f1 = __half22float2(h1);

    float* p = out + (size_t)d * D + c * 4;
    asm volatile("red.global.add.v4.f32 [%0], {%1, %2, %3, %4};"
                 :: "l"(p), "f"(a * f0.x), "f"(a * f0.y),
                    "f"(a * f1.x), "f"(a * f1.y)
                 : "memory");
}

// ---------------------------------------------------------------------------
// Finalize: out = relu(out + b), in place, float4-vectorized.
// ---------------------------------------------------------------------------
__global__ void finalize_kernel(float4* __restrict__ out,
                                const float4* __restrict__ b4) {
    int i = blockIdx.x * blockDim.x + threadIdx.x;
    int total = N_NODES * D4;
    if (i >= total) return;
    int c = i % D4;
    float4 bv = b4[c];
    float4 v = out[i];
    v.x = fmaxf(v.x + bv.x, 0.f);
    v.y = fmaxf(v.y + bv.y, 0.f);
    v.z = fmaxf(v.z + bv.z, 0.f);
    v.w = fmaxf(v.w + bv.w, 0.f);
    out[i] = v;
}

extern "C" void kernel_launch(void* const* d_in, const int* in_sizes, int n_in,
                              void* d_out, int out_size) {
    const float* x        = (const float*)d_in[0];
    const float* w        = (const float*)d_in[1];
    const float* b        = (const float*)d_in[2];
    const int*   edge_src = (const int*)d_in[3];
    const int*   edge_dst = (const int*)d_in[4];
    const float* adj_vals = (const float*)d_in[5];
    float* out = (float*)d_out;

    const int threads = 256;

    // 1) zero output (coalesced)
    {
        int total = N_NODES * D4;
        zero_kernel<<<(total + threads - 1) / threads, threads>>>((float4*)out);
    }
    // 2) xw = x @ w (fp16 store), 2 nodes/thread
    {
        int nodes_per_block = 2 * threads;
        int blocks = (N_NODES + nodes_per_block - 1) / nodes_per_block;
        gemm_kernel<<<blocks, threads>>>(x, w);
    }
    // 3) scatter-add over edges (fp16 gather, contiguous fp32 vector RED)
    {
        int total = N_EDGES * D4;
        scatter_kernel<<<(total + threads - 1) / threads, threads>>>(
            edge_src, edge_dst, adj_vals, out);
    }
    // 4) out = relu(out + b)
    {
        int total = N_NODES * D4;
        finalize_kernel<<<(total + threads - 1) / threads, threads>>>(
            (float4*)out, (const float4*)b);
    }
}